// round 16
// baseline (speedup 1.0000x reference)
#include <cuda_runtime.h>
#include <cuda_bf16.h>

#define BB 32
#define TT 400
#define DD 1024
#define VV 5000
#define LL 100
#define L1 101
#define NEGBIG -1e30f
#define NBLK 148
// smem: pinned Wc0x tile 135168B | stream region 69632B | mbarriers 32B
#define PIN 135168
#define MBAR_OFF 204800
#define SMSZ 204928
#define BIG_SMEM 110592

__device__ __align__(16) __nv_bfloat16 g_hsb [BB * TT * DD];
__device__ __align__(16) __nv_bfloat16 g_preb[BB * TT * DD];
__device__ __align__(16) __nv_bfloat16 g_eysb[L1 * BB * DD];
__device__ __align__(16) __nv_bfloat16 g_Wencb[DD * DD];
__device__ __align__(16) __nv_bfloat16 g_Wdecb[DD * DD];
__device__ __align__(16) __nv_bfloat16 g_Woutb[VV * 2048];
__device__ __align__(16) __nv_bfloat16 g_Wc0e[4096 * 1024];
__device__ __align__(16) __nv_bfloat16 g_Wc0x[4096 * 2048];
__device__ __align__(16) __nv_bfloat16 g_Wc1p[128 * 16 * 32 * 136];
__device__ __align__(16) float g_bs0r[4096];
__device__ __align__(16) float g_bs1r[4096];
__device__ __align__(16) float g_emb0[(long long)L1 * BB * 4096];
__device__ __align__(16) __nv_bfloat16 g_dqb[BB * DD];
__device__ __align__(16) __nv_bfloat16 g_attb[BB * DD];
__device__ __align__(16) __nv_bfloat16 g_z0s[2][BB * DD];
__device__ __align__(16) __nv_bfloat16 g_z0p[2][8 * 32 * 136];
__device__ __align__(16) __nv_bfloat16 g_z1p[2][8 * 32 * 136];
__device__ __align__(16) float g_c0[BB * DD];
__device__ __align__(16) float g_c1[BB * DD];
__device__ __align__(16) float g_pc[148 * 1024];
__device__ __align__(16) float g_ms[304];
__device__ unsigned g_cmb[32];
__device__ __align__(16) __nv_bfloat16 g_zallb[L1 * BB * 2048];
__device__ __align__(16) unsigned long long g_lse[3328];
__device__ __align__(16) float g_tgtl[3328];
__device__ int g_i64;
__device__ unsigned g_arrive;
__device__ unsigned g_release;
__device__ unsigned g_dqf;

__device__ __forceinline__ float sigm(float x) { return 1.0f / (1.0f + expf(-x)); }
__device__ __forceinline__ int read_ys(const void* ys, int i) {
    return g_i64 ? (int)((const long long*)ys)[i] : ((const int*)ys)[i];
}
__device__ __forceinline__ unsigned sptr(const void* p) {
    unsigned r;
    asm("{.reg .u64 t; cvta.to.shared.u64 t, %1; cvt.u32.u64 %0, t;}" : "=r"(r) : "l"(p));
    return r;
}
__device__ __forceinline__ void cpa16(unsigned s, const void* g) {
    asm volatile("cp.async.cg.shared.global [%0], [%1], 16;" :: "r"(s), "l"(g));
}
#define CP_COMMIT asm volatile("cp.async.commit_group;")
#define CP_WAIT2  asm volatile("cp.async.wait_group 2;")
#define CP_WAIT1  asm volatile("cp.async.wait_group 1;")
#define CP_WAIT0  asm volatile("cp.async.wait_group 0;")

#define MWAIT(mb, ph) do {                                                          \
    unsigned _done;                                                                 \
    do {                                                                            \
        asm volatile("{.reg .pred p; "                                              \
                     "mbarrier.try_wait.parity.acquire.cta.shared::cta.b64 p, [%1], %2; " \
                     "selp.b32 %0,1,0,p;}"                                          \
                     : "=r"(_done) : "r"(mb), "r"((unsigned)(ph)) : "memory");      \
    } while (!_done);                                                               \
} while (0)

__device__ __forceinline__ void bulkcp(unsigned sa, const void* g, unsigned bytes, unsigned mb) {
    asm volatile("cp.async.bulk.shared::cta.global.mbarrier::complete_tx::bytes [%0], [%1], %2, [%3];"
                 :: "r"(sa), "l"(g), "r"(bytes), "r"(mb) : "memory");
}
__device__ __forceinline__ void mexpect(unsigned mb, unsigned bytes) {
    asm volatile("mbarrier.arrive.expect_tx.shared.b64 _, [%0], %1;" :: "r"(mb), "r"(bytes) : "memory");
}

__device__ __forceinline__ unsigned pack2(float a, float b) {
    __nv_bfloat162 p = __floats2bfloat162_rn(a, b);
    return *(unsigned*)&p;
}

// ---------------------------------------------------------------- fused prologue
__global__ void k_prep_all(
    const float* __restrict__ hs, const float* __restrict__ embed,
    const float* __restrict__ Wenc, const float* __restrict__ Wdec,
    const float* __restrict__ Wout,
    const float* __restrict__ Wih0, const float* __restrict__ Whh0,
    const float* __restrict__ Wih1, const float* __restrict__ Whh1,
    const float* __restrict__ bih0, const float* __restrict__ bhh0,
    const float* __restrict__ bih1, const float* __restrict__ bhh1,
    const void* __restrict__ ys)
{
    __shared__ int s_i64;
    const int tid = threadIdx.x;
    if (tid == 0) {
        const int* w = (const int*)ys;
        int f = 1;
        for (int j = 1; j < 64; j += 2) if (w[j] != 0) f = 0;
        s_i64 = f;
    }
    __syncthreads();
    const int i64 = s_i64;
    const long long gi = (long long)blockIdx.x * blockDim.x + tid;
    const long long gn = (long long)gridDim.x * blockDim.x;

    {
        __nv_bfloat16 z = __float2bfloat16(0.f);
        for (long long j = gi; j < BB * DD; j += gn) {
            g_c0[j] = 0.f; g_c1[j] = 0.f;
            g_z0s[0][j] = z; g_z0s[1][j] = z;
        }
        for (long long j = gi; j < 8 * 32 * 136; j += gn) {
            g_z0p[0][j] = z; g_z0p[1][j] = z;
            g_z1p[0][j] = z; g_z1p[1][j] = z;
        }
        for (long long j = gi; j < 4096; j += gn) {
            int u = (int)j >> 2, gate = (int)j & 3;
            int orow = gate * 1024 + u;
            g_bs0r[j] = bih0[orow] + bhh0[orow];
            g_bs1r[j] = bih1[orow] + bhh1[orow];
        }
        unsigned long long neg = ((unsigned long long)(unsigned)__float_as_int(NEGBIG) << 32);
        for (long long j = gi; j < 3328; j += gn) { g_lse[j] = neg; g_tgtl[j] = 0.f; }
        if (gi < 32) g_cmb[gi] = 0u;
        if (gi == 0) { g_arrive = 0u; g_release = 0u; g_dqf = 0u; g_i64 = i64; }
    }
    {
        const float4* s = (const float4*)hs;
        uint4* d = (uint4*)g_hsb;
        for (long long j = gi; j < 1638400LL; j += gn) {
            float4 a = s[2 * j], b = s[2 * j + 1];
            d[j] = make_uint4(pack2(a.x, a.y), pack2(a.z, a.w), pack2(b.x, b.y), pack2(b.z, b.w));
        }
    }
    {
        const float4* s = (const float4*)Wenc;
        uint4* d = (uint4*)g_Wencb;
        for (long long j = gi; j < 131072LL; j += gn) {
            float4 a = s[2 * j], b = s[2 * j + 1];
            d[j] = make_uint4(pack2(a.x, a.y), pack2(a.z, a.w), pack2(b.x, b.y), pack2(b.z, b.w));
        }
    }
    {
        const float4* s = (const float4*)Wdec;
        uint4* d = (uint4*)g_Wdecb;
        for (long long j = gi; j < 131072LL; j += gn) {
            float4 a = s[2 * j], b = s[2 * j + 1];
            d[j] = make_uint4(pack2(a.x, a.y), pack2(a.z, a.w), pack2(b.x, b.y), pack2(b.z, b.w));
        }
    }
    {
        const float4* s = (const float4*)Wout;
        uint4* d = (uint4*)g_Woutb;
        for (long long j = gi; j < 1280000LL; j += gn) {
            float4 a = s[2 * j], b = s[2 * j + 1];
            d[j] = make_uint4(pack2(a.x, a.y), pack2(a.z, a.w), pack2(b.x, b.y), pack2(b.z, b.w));
        }
    }
    {
        for (long long it = gi; it < 413696LL; it += gn) {
            int row = (int)(it >> 7), col = (int)(it & 127);
            int l = row >> 5, b = row & 31;
            int tok = 4999;
            if (l > 0) {
                int idx = b * LL + l - 1;
                tok = i64 ? (int)((const long long*)ys)[idx] : ((const int*)ys)[idx];
            }
            float4 v = ((const float4*)(embed + (long long)tok * 1024))[col];
            ((uint2*)(g_eysb + (long long)row * 1024))[col] = make_uint2(pack2(v.x, v.y), pack2(v.z, v.w));
        }
    }
    {
        for (long long j4 = gi; j4 < 1048576LL; j4 += gn) {
            long long j = j4 * 4;
            int r = (int)(j >> 10), c = (int)(j & 1023);
            long long orow = (r & 3) * 1024 + (r >> 2);
            float4 v = *(const float4*)(Wih0 + orow * 2048 + c);
            *(uint2*)(g_Wc0e + j) = make_uint2(pack2(v.x, v.y), pack2(v.z, v.w));
        }
    }
    {
        for (long long j4 = gi; j4 < 2097152LL; j4 += gn) {
            long long j = j4 * 4;
            int r = (int)(j >> 11), c = (int)(j & 2047);
            long long orow = (r & 3) * 1024 + (r >> 2);
            float4 v = (c < 1024) ? *(const float4*)(Wih0 + orow * 2048 + 1024 + c)
                                  : *(const float4*)(Whh0 + orow * 1024 + (c - 1024));
            *(uint2*)(g_Wc0x + j) = make_uint2(pack2(v.x, v.y), pack2(v.z, v.w));
        }
    }
    // Wc1 padded chunk layout: [tile][kc][r][c], c<128 real (gate-interleaved)
    {
        const long long N4 = 128LL * 16 * 32 * 136 / 4;
        for (long long j4 = gi; j4 < N4; j4 += gn) {
            long long j = j4 * 4;
            int tile = (int)(j / 69632);
            int rem  = (int)(j % 69632);
            int kc = rem / 4352;
            int r  = (rem % 4352) / 136;
            int c  = rem % 136;
            uint2 out = make_uint2(0u, 0u);
            if (c < 128) {
                int rg = tile * 32 + r;
                long long orow = (rg & 3) * 1024 + (rg >> 2);
                int cc = kc * 128 + c;
                float4 v = (cc < 1024) ? *(const float4*)(Wih1 + orow * 1024 + cc)
                                       : *(const float4*)(Whh1 + orow * 1024 + (cc - 1024));
                out = make_uint2(pack2(v.x, v.y), pack2(v.z, v.w));
            }
            *(uint2*)(g_Wc1p + j) = out;
        }
    }
}

__device__ __forceinline__ void mma_bf16(float* d, const unsigned* a, const unsigned* b) {
    asm volatile(
        "mma.sync.aligned.m16n8k16.row.col.f32.bf16.bf16.f32 "
        "{%0,%1,%2,%3}, {%4,%5,%6,%7}, {%8,%9}, {%0,%1,%2,%3};\n"
        : "+f"(d[0]), "+f"(d[1]), "+f"(d[2]), "+f"(d[3])
        : "r"(a[0]), "r"(a[1]), "r"(a[2]), "r"(a[3]), "r"(b[0]), "r"(b[1]));
}

// ---------------------------------------------------------------- big GEMM
// EPI 0: fp32 out + bias. EPI 1: tanh -> bf16 out. EPI 2: fused CE partials.
#define BKP 72
__device__ __forceinline__ void issue_big(
    char* smb, int slot, int k0,
    const __nv_bfloat16* A, const __nv_bfloat16* B,
    int M, int N, int K, int m0, int n0)
{
    __nv_bfloat16* smA = (__nv_bfloat16*)smb + slot * (2 * 128 * BKP);
    __nv_bfloat16* smB = smA + 128 * BKP;
    const int tid = threadIdx.x;
#pragma unroll
    for (int j = 0; j < 4; j++) {
        int idx = tid + j * 256;
        int r = idx >> 3, c = (idx & 7) * 8;
        int m = m0 + r; if (m >= M) m = 0;
        cpa16(sptr(smA + r * BKP + c), A + (long long)m * K + k0 + c);
        int n = n0 + r; if (n >= N) n = 0;
        cpa16(sptr(smB + r * BKP + c), B + (long long)n * K + k0 + c);
    }
}

template <int EPI>
__global__ __launch_bounds__(256) void mma_big(
    const __nv_bfloat16* __restrict__ A, const __nv_bfloat16* __restrict__ B,
    const float* __restrict__ bias, float* __restrict__ Cf,
    __nv_bfloat16* __restrict__ Cb, int M, int N, int K,
    const void* __restrict__ ys)
{
    extern __shared__ char smb[];
    const int tid = threadIdx.x, lane = tid & 31, wid = tid >> 5;
    const int wm = wid >> 1, wn = wid & 1;
    const int m0 = blockIdx.y * 128, n0 = blockIdx.x * 128;
    const int g = lane >> 2, tg = lane & 3;
    const int S = K >> 6;

    float acc[2][8][4];
#pragma unroll
    for (int a = 0; a < 2; a++)
#pragma unroll
        for (int b = 0; b < 8; b++)
#pragma unroll
            for (int c = 0; c < 4; c++) acc[a][b][c] = 0.f;

    issue_big(smb, 0, 0, A, B, M, N, K, m0, n0); CP_COMMIT;
    if (S > 1) issue_big(smb, 1, 64, A, B, M, N, K, m0, n0);
    CP_COMMIT;

    for (int si = 0; si < S; si++) {
        CP_WAIT1;
        __syncthreads();
        if (si + 2 < S) issue_big(smb, (si + 2) % 3, (si + 2) << 6, A, B, M, N, K, m0, n0);
        CP_COMMIT;
        __nv_bfloat16 (*As)[BKP] = (__nv_bfloat16(*)[BKP])((__nv_bfloat16*)smb + (si % 3) * (2 * 128 * BKP));
        __nv_bfloat16 (*Bs)[BKP] = (__nv_bfloat16(*)[BKP])((__nv_bfloat16*)smb + (si % 3) * (2 * 128 * BKP) + 128 * BKP);
#pragma unroll
        for (int kt = 0; kt < 4; kt++) {
            const int c0 = kt * 16 + tg * 2;
            unsigned af[2][4];
#pragma unroll
            for (int mt = 0; mt < 2; mt++) {
                int r = wm * 32 + mt * 16 + g;
                af[mt][0] = *(const unsigned*)&As[r][c0];
                af[mt][1] = *(const unsigned*)&As[r + 8][c0];
                af[mt][2] = *(const unsigned*)&As[r][c0 + 8];
                af[mt][3] = *(const unsigned*)&As[r + 8][c0 + 8];
            }
#pragma unroll
            for (int nt = 0; nt < 8; nt++) {
                int n = wn * 64 + nt * 8 + g;
                unsigned bf[2];
                bf[0] = *(const unsigned*)&Bs[n][c0];
                bf[1] = *(const unsigned*)&Bs[n][c0 + 8];
                mma_bf16(acc[0][nt], af[0], bf);
                mma_bf16(acc[1][nt], af[1], bf);
            }
        }
    }

    if (EPI == 0 || EPI == 1) {
#pragma unroll
        for (int mt = 0; mt < 2; mt++) {
#pragma unroll
            for (int nt = 0; nt < 8; nt++) {
                int r = m0 + wm * 32 + mt * 16 + g;
                int c = n0 + wn * 64 + nt * 8 + tg * 2;
                float* a = acc[mt][nt];
                if (EPI == 0) {
                    float b0 = (c < N) ? bias[c] : 0.f;
                    float b1 = (c + 1 < N) ? bias[c + 1] : 0.f;
                    if (r < M) {
                        if (c < N)     Cf[(long long)r * N + c]     = a[0] + b0;
                        if (c + 1 < N) Cf[(long long)r * N + c + 1] = a[1] + b1;
                    }
                    if (r + 8 < M) {
                        if (c < N)     Cf[(long long)(r + 8) * N + c]     = a[2] + b0;
                        if (c + 1 < N) Cf[(long long)(r + 8) * N + c + 1] = a[3] + b1;
                    }
                } else {
                    float b0 = bias[c], b1 = bias[c + 1];
                    __nv_bfloat162 v0 = __floats2bfloat162_rn(tanhf(a[0] + b0), tanhf(a[1] + b1));
                    __nv_bfloat162 v1 = __floats2bfloat162_rn(tanhf(a[2] + b0), tanhf(a[3] + b1));
                    *(__nv_bfloat162*)(Cb + (long long)r * N + c) = v0;
                    *(__nv_bfloat162*)(Cb + (long long)(r + 8) * N + c) = v1;
                }
            }
        }
    } else {
        // EPI == 2: fused cross-entropy partials
        __syncthreads();
        float* rmax = (float*)smb;          // [128][2]
        float* rsum = rmax + 256;           // [128][2]
        int lrow[4];
        float lmax[4];
#pragma unroll
        for (int mt = 0; mt < 2; mt++)
#pragma unroll
            for (int hf = 0; hf < 2; hf++) {
                lrow[mt * 2 + hf] = wm * 32 + mt * 16 + g + hf * 8;
                lmax[mt * 2 + hf] = NEGBIG;
            }
#pragma unroll
        for (int mt = 0; mt < 2; mt++)
#pragma unroll
            for (int nt = 0; nt < 8; nt++) {
                int cb = n0 + wn * 64 + nt * 8 + tg * 2;
#pragma unroll
                for (int j = 0; j < 2; j++) {
                    int c = cb + j;
                    if (c < N) {
                        float bv = bias[c];
                        lmax[mt * 2 + 0] = fmaxf(lmax[mt * 2 + 0], acc[mt][nt][j] + bv);
                        lmax[mt * 2 + 1] = fmaxf(lmax[mt * 2 + 1], acc[mt][nt][2 + j] + bv);
                    }
                }
            }
#pragma unroll
        for (int i = 0; i < 4; i++) {
            lmax[i] = fmaxf(lmax[i], __shfl_xor_sync(0xffffffffu, lmax[i], 1));
            lmax[i] = fmaxf(lmax[i], __shfl_xor_sync(0xffffffffu, lmax[i], 2));
        }
        if (tg == 0) {
#pragma unroll
            for (int i = 0; i < 4; i++) rmax[lrow[i] * 2 + wn] = lmax[i];
        }
        __syncthreads();
        float fm[4];
        int tgt[4];
#pragma unroll
        for (int i = 0; i < 4; i++) {
            fm[i] = fmaxf(rmax[lrow[i] * 2], rmax[lrow[i] * 2 + 1]);
            int r = m0 + lrow[i];
            if (r < M) {
                int l = r >> 5, bb = r & 31;
                tgt[i] = (l < LL) ? read_ys(ys, bb * LL + l) : 4999;
            } else tgt[i] = -1;
        }
        float lsum[4] = {0.f, 0.f, 0.f, 0.f};
#pragma unroll
        for (int mt = 0; mt < 2; mt++)
#pragma unroll
            for (int nt = 0; nt < 8; nt++) {
                int cb = n0 + wn * 64 + nt * 8 + tg * 2;
#pragma unroll
                for (int j = 0; j < 2; j++) {
                    int c = cb + j;
                    if (c < N) {
                        float bv = bias[c];
                        float v0 = acc[mt][nt][j] + bv;
                        float v1 = acc[mt][nt][2 + j] + bv;
                        lsum[mt * 2 + 0] += expf(v0 - fm[mt * 2 + 0]);
                        lsum[mt * 2 + 1] += expf(v1 - fm[mt * 2 + 1]);
                        if (c == tgt[mt * 2 + 0]) g_tgtl[m0 + lrow[mt * 2 + 0]] = v0;
                        if (c == tgt[mt * 2 + 1]) g_tgtl[m0 + lrow[mt * 2 + 1]] = v1;
                    }
                }
            }
#pragma unroll
        for (int i = 0; i < 4; i++) {
            lsum[i] += __shfl_xor_sync(0xffffffffu, lsum[i], 1);
            lsum[i] += __shfl_xor_sync(0xffffffffu, lsum[i], 2);
        }
        if (tg == 0) {
#pragma unroll
            for (int i = 0; i < 4; i++) rsum[lrow[i] * 2 + wn] = lsum[i];
        }
        __syncthreads();
        if (tid < 128) {
            int r = m0 + tid;
            if (r < M) {
                float mv = fmaxf(rmax[tid * 2], rmax[tid * 2 + 1]);
                float sv = rsum[tid * 2] + rsum[tid * 2 + 1];
                unsigned long long old = g_lse[r], assumed;
                do {
                    assumed = old;
                    float om = __int_as_float((int)(assumed >> 32));
                    float os = __int_as_float((int)(assumed & 0xffffffffULL));
                    float nm = fmaxf(om, mv);
                    float ns = os * expf(om - nm) + sv * expf(mv - nm);
                    unsigned long long nv =
                        ((unsigned long long)(unsigned)__float_as_int(nm) << 32) |
                        (unsigned)__float_as_int(ns);
                    old = atomicCAS(&g_lse[r], assumed, nv);
                } while (old != assumed);
            }
        }
    }
}

// ---------------------------------------------------------------- barrier
__device__ __forceinline__ void gbar(int e) {
    __syncthreads();
    if (threadIdx.x == 0) {
        __threadfence();
        unsigned old = atomicAdd(&g_arrive, 1u);
        if (old == (unsigned)e * NBLK + (NBLK - 1)) {
            atomicExch(&g_release, (unsigned)(e + 1));
        } else {
            unsigned r;
            do { asm volatile("ld.global.cg.u32 %0, [%1];" : "=r"(r) : "l"(&g_release)); }
            while (r < (unsigned)(e + 1));
        }
        __threadfence();
    }
    __syncthreads();
}

// ---------------------------------------------------------------- dq tile GEMM (cp.async, round-13)
__device__ __forceinline__ void issue_dq(char* smraw, int slot, int kc,
                                         const __nv_bfloat16* A0, const __nv_bfloat16* B, int n0)
{
    constexpr int ASZ = 32 * 264;
    constexpr int STE = ASZ + 64 * 264;
    __nv_bfloat16* smA = (__nv_bfloat16*)smraw + slot * STE;
    __nv_bfloat16* smB = smA + ASZ;
    const int tid = threadIdx.x;
    const int kbase = kc << 8;
#pragma unroll
    for (int j = 0; j < 4; j++) {
        int u = tid + j * 256;
        int r = u >> 5, c = (u & 31) << 3;
        cpa16(sptr(smA + r * 264 + c), A0 + r * 1024 + kbase + c);
    }
#pragma unroll
    for (int j = 0; j < 8; j++) {
        int u = tid + j * 256;
        int r = u >> 5, c = (u & 31) << 3;
        cpa16(sptr(smB + r * 264 + c), B + (long long)(n0 + r) * 1024 + kbase + c);
    }
}

__device__ void gtile_dq(char* smraw, int n0, const __nv_bfloat16* __restrict__ B,
                         const float* __restrict__ bias, const __nv_bfloat16* A0,
                         __nv_bfloat16* outb)
{
    constexpr int ASZ = 32 * 264;
    constexpr int STE = ASZ + 64 * 264;
    constexpr int NW = 32 * 64;
    const int tid = threadIdx.x, lane = tid & 31, wid = tid >> 5;
    const int g = lane >> 2, tg = lane & 3;
    const int S = 4;

    float acc[2][8][4];
#pragma unroll
    for (int a = 0; a < 2; a++)
#pragma unroll
        for (int b = 0; b < 8; b++)
#pragma unroll
            for (int c = 0; c < 4; c++) acc[a][b][c] = 0.f;

#pragma unroll
    for (int st = 0; st < 3; st++) {
        if (st < S) issue_dq(smraw, st, st, A0, B, n0);
        CP_COMMIT;
    }

    for (int si = 0; si < S; si++) {
        CP_WAIT2;
        __syncthreads();
        int nx = si + 3;
        if (nx < S) issue_dq(smraw, nx & 3, nx, A0, B, n0);
        CP_COMMIT;
        __nv_bfloat16 (*As)[264] = (__nv_bfloat16(*)[264])((__nv_bfloat16*)smraw + (si & 3) * STE);
        __nv_bfloat16 (*Bs)[264] = (__nv_bfloat16(*)[264])((__nv_bfloat16*)smraw + (si & 3) * STE + ASZ);
#pragma unroll
        for (int ks = 0; ks < 2; ks++) {
            const int c0 = wid * 32 + ks * 16 + tg * 2;
            unsigned af[2][4];
#pragma unroll
            for (int mt = 0; mt < 2; mt++) {
                int r = mt * 16 + g;
                af[mt][0] = *(const unsigned*)&As[r][c0];
                af[mt][1] = *(const unsigned*)&As[r + 8][c0];
                af[mt][2] = *(const unsigned*)&As[r][c0 + 8];
                af[mt][3] = *(const unsigned*)&As[r + 8][c0 + 8];
            }
#pragma unroll
            for (int nt = 0; nt < 8; nt++) {
                int n = nt * 8 + g;
                unsigned bf[2];
                bf[0] = *(const unsigned*)&Bs[n][c0];
                bf[1] = *(const unsigned*)&Bs[n][c0 + 8];
                mma_bf16(acc[0][nt], af[0], bf);
                mma_bf16(acc[1][nt], af[1], bf);
            }
        }
    }
    __syncthreads();

    float* Pred = (float*)smraw;
    {
        int base = wid * NW;
#pragma unroll
        for (int mt = 0; mt < 2; mt++)
#pragma unroll
            for (int nt = 0; nt < 8; nt++) {
                int r = mt * 16 + g, cl = nt * 8 + tg * 2;
                Pred[base + r * 64 + cl]           = acc[mt][nt][0];
                Pred[base + r * 64 + cl + 1]       = acc[mt][nt][1];
                Pred[base + (r + 8) * 64 + cl]     = acc[mt][nt][2];
                Pred[base + (r + 8) * 64 + cl + 1] = acc[mt][nt][3];
            }
    }
    __syncthreads();

    for (int o = tid; o < NW; o += 256) {
        int r = o >> 6, c = o & 63;
        float sum = 0.f;
#pragma unroll
        for (int w = 0; w < 8; w++) sum += Pred[w * NW + o];
        outb[r * 1024 + n0 + c] = __float2bfloat16(tanhf(sum + bias[n0 + c]));
    }
    __syncthreads();
}

// ---------------------------------------------------------------- g1: bulk-copy + mbarrier pipeline
__device__ __forceinline__ void issue_g1b(char* stream, unsigned mbar0, int kc,
                                          const __nv_bfloat16* z0p, const __nv_bfloat16* z1p,
                                          const __nv_bfloat16* Bw)
{
    unsigned mb = mbar0 + (kc & 3) * 8;
    mexpect(mb, 17408u);
    const __nv_bfloat16* asrc = (kc < 8) ? (z0p + kc * 4352) : (z1p + (kc - 8) * 4352);
    unsigned sa = sptr(stream + (kc & 3) * 17408);
    bulkcp(sa, asrc, 8704u, mb);
    bulkcp(sa + 8704u, Bw + kc * 4352, 8704u, mb);
}

__device__ void gtile_g1(char* stream, unsigned mbar0, int* par, int tile,
                         const __nv_bfloat16* z0p, const __nv_bfloat16* z1p,
                         float* cst, __nv_bfloat16* z1po, __nv_bfloat16* zallp, int step)
{
    const int tid = threadIdx.x, lane = tid & 31, wid = tid >> 5;
    const int g = lane >> 2, tg = lane & 3;
    const __nv_bfloat16* Bw = g_Wc1p + (long long)tile * 69632;

    float acc[2][4][4];
#pragma unroll
    for (int a = 0; a < 2; a++)
#pragma unroll
        for (int b = 0; b < 4; b++)
#pragma unroll
            for (int c = 0; c < 4; c++) acc[a][b][c] = 0.f;

    if (tid == 0) {
        issue_g1b(stream, mbar0, 0, z0p, z1p, Bw);
        issue_g1b(stream, mbar0, 1, z0p, z1p, Bw);
        issue_g1b(stream, mbar0, 2, z0p, z1p, Bw);
    }

    for (int si = 0; si < 16; si++) {
        {
            unsigned mb = mbar0 + (si & 3) * 8;
            MWAIT(mb, par[si & 3]);
            par[si & 3] ^= 1;
        }
        __syncthreads();
        if (tid == 0 && si + 3 < 16) issue_g1b(stream, mbar0, si + 3, z0p, z1p, Bw);
        __nv_bfloat16 (*As)[136] = (__nv_bfloat16(*)[136])(stream + (si & 3) * 17408);
        __nv_bfloat16 (*Bs)[136] = (__nv_bfloat16(*)[136])(stream + (si & 3) * 17408 + 8704);
        const int c0 = wid * 16 + tg * 2;
        unsigned af[2][4];
#pragma unroll
        for (int mt = 0; mt < 2; mt++) {
            int r = mt * 16 + g;
            af[mt][0] = *(const unsigned*)&As[r][c0];
            af[mt][1] = *(const unsigned*)&As[r + 8][c0];
            af[mt][2] = *(const unsigned*)&As[r][c0 + 8];
            af[mt][3] = *(const unsigned*)&As[r + 8][c0 + 8];
        }
#pragma unroll
        for (int nt = 0; nt < 4; nt++) {
            int n = nt * 8 + g;
            unsigned bf[2];
            bf[0] = *(const unsigned*)&Bs[n][c0];
            bf[1] = *(const unsigned*)&Bs[n][c0 + 8];
            mma_bf16(acc[0][nt], af[0], bf);
            mma_bf16(acc[1][nt], af[1], bf);
        }
    }
    __syncthreads();

    float* Pred = (float*)stream;
    {
        int base = wid * 1024;
#pragma unroll
        for (int mt = 0; mt < 2; mt++)
#pragma unroll
            for (int nt = 0; nt < 4; nt++) {
                int r = mt * 16 + g, cl = nt * 8 + tg * 2;
                Pred[base + r * 32 + cl]           = acc[mt][nt][0];
                Pred[base + r * 32 + cl + 1]       = acc[mt][nt][1];
                Pred[base + (r + 8) * 32 + cl]     = acc[mt][nt][2];
                Pred[base + (r + 8) * 32 + cl + 1] = acc[mt][nt][3];
            }
    }
    __syncthreads();
    {
        const int n0 = tile * 32;
        int b = tid >> 3, ul = tid & 7;
        float gv[4];
#pragma unroll
        for (int gate = 0; gate < 4; gate++) {
            int col = ul * 4 + gate;
            float sum = 0.f;
#pragma unroll
            for (int w = 0; w < 8; w++) sum += Pred[w * 1024 + b * 32 + col];
            gv[gate] = sum + g_bs1r[n0 + col];
        }
        int u = (n0 >> 2) + ul;
        int gid = b * 1024 + u;
        float cv = sigm(gv[1]) * cst[gid] + sigm(gv[0]) * tanhf(gv[2]);
        float h = sigm(gv[3]) * tanhf(cv);
        cst[gid] = cv;
        z1po[(u >> 7) * 4352 + b * 136 + (u & 127)] = __float2bfloat16(h);
        zallp[(long long)(step * 32 + b) * 2048 + u] = __float2bfloat16(h);
    }
    __syncthreads();
}

// ---------------------------------------------------------------- g0 (B pinned, A cp.async — round-13)
__device__ __forceinline__ void issue_g0a(char* strm, int slot, int kc,
                                          const __nv_bfloat16* A0, const __nv_bfloat16* A1)
{
    __nv_bfloat16* smA = (__nv_bfloat16*)strm + slot * (32 * 264);
    const int tid = threadIdx.x;
    const int kbase = kc << 8;
    const int region = kbase >> 10;
    const int koff = kbase & 1023;
#pragma unroll
    for (int j = 0; j < 4; j++) {
        int u = tid + j * 256;
        int r = u >> 5, c = (u & 31) << 3;
        const __nv_bfloat16* src = (region == 0 ? A0 : A1) + r * 1024 + koff + c;
        cpa16(sptr(smA + r * 264 + c), src);
    }
}

__device__ void gtile_g0pin(char* sm, int n0,
                            const __nv_bfloat16* A0, const __nv_bfloat16* A1,
                            float* cst, __nv_bfloat16* znew, __nv_bfloat16* z0po,
                            int step, const float* eb)
{
    char* strm = sm + PIN;
    const int tid = threadIdx.x, lane = tid & 31, wid = tid >> 5;
    const int g = lane >> 2, tg = lane & 3;
    const int S = 8;

    float acc[2][4][4];
#pragma unroll
    for (int a = 0; a < 2; a++)
#pragma unroll
        for (int b = 0; b < 4; b++)
#pragma unroll
            for (int c = 0; c < 4; c++) acc[a][b][c] = 0.f;

#pragma unroll
    for (int st = 0; st < 3; st++) {
        issue_g0a(strm, st, st, A0, A1);
        CP_COMMIT;
    }

    for (int si = 0; si < S; si++) {
        CP_WAIT2;
        __syncthreads();
        int nx = si + 3;
        if (nx < S) issue_g0a(strm, nx & 3, nx, A0, A1);
        CP_COMMIT;
        __nv_bfloat16 (*As)[264] = (__nv_bfloat16(*)[264])((__nv_bfloat16*)strm + (si & 3) * (32 * 264));
        __nv_bfloat16 (*Bs)[264] = (__nv_bfloat16(*)[264])((__nv_bfloat16*)sm + si * (32 * 264));
#pragma unroll
        for (int ks = 0; ks < 2; ks++) {
            const int c0 = wid * 32 + ks * 16 + tg * 2;
            unsigned af[2][4];
#pragma unroll
            for (int mt = 0; mt < 2; mt++) {
                int r = mt * 16 + g;
                af[mt][0] = *(const unsigned*)&As[r][c0];
                af[mt][1] = *(const unsigned*)&As[r + 8][c0];
                af[mt][2] = *(const unsigned*)&As[r][c0 + 8];
                af[mt][3] = *(const unsigned*)&As[r + 8][c0 + 8];
            }
#pragma unroll
            for (int nt = 0; nt < 4; nt++) {
                int n = nt * 8 + g;
                unsigned bf[2];
                bf[0] = *(const unsigned*)&Bs[n][c0];
                bf[1] = *(const unsigned*)&Bs[n][c0 + 8];
                mma_bf16(acc[0][nt], af[0], bf);
                mma_bf16(acc[1][nt], af[1], bf);
            }
        }
    }
    __syncthreads();

    float* Pred = (float*)strm;
    {
        int base = wid * 1024;
#pragma unroll
        for (int mt = 0; mt < 2; mt++)
#pragma unroll
            for (int nt = 0; nt < 4; nt++) {
                int r = mt * 16 + g, cl = nt * 8 + tg * 2;
                Pred[base + r * 32 + cl]           = acc[mt][nt][0];
                Pred[base + r * 32 + cl + 1]       = acc[mt][nt][1];
                Pred[base + (r + 8) * 32 + cl]     = acc[mt][nt][2];
                Pred[base + (r + 8) * 32 + cl + 1] = acc[mt][nt][3];
            }
    }
    __syncthreads();
    {
        int b = tid >> 3, ul = tid & 7;
        float gv[4];
#pragma unroll
        for (int gate = 0; gate < 4; gate++) {
            int col = ul * 4 + gate;
            float sum = 0.f;
#pragma unroll
            for (int w = 0; w < 8; w++) sum += Pred[w * 1024 + b * 32 + col];
            gv[gate] = sum + eb[b * 4096 + n0 + col];
        }
        int u = (n0 >> 2) + ul;
        int gid = b * 1024 + u;
        float cv = sigm(gv[1]) * cst[gid] + sigm(gv[0]) * tanhf(gv[2]);
        float h = sigm(gv[3]) * tanhf(cv);
        cst[gid] = cv;
        __nv_bfloat16 hb = __float2bfloat16(h);
        znew[gid] = hb;
        z0po[(u >> 7) * 4352 + b * 136 + (u & 127)] = hb;
    }
    __syncthreads();
}

// ---------------------------------------------------------------- attention (hlen-skip)
__device__ void phase_epc(char* smraw, int s, const int* __restrict__ hlens) {
    const int bid = blockIdx.x;
    int b, t0, tlen, ncs, base;
    if (bid < 100) { b = bid / 5; t0 = (bid % 5) * 80; tlen = 80; ncs = 5; base = b * 5; }
    else { int u = bid - 100; b = 20 + (u >> 2); t0 = (u & 3) * 100; tlen = 100; ncs = 4; base = 100 + (b - 20) * 4; }

    const int tid = threadIdx.x, lane = tid & 31, wid = tid >> 5;
    float* dqs = (float*)smraw;
    float* ws  = dqs + 1024;
    float* red = ws + 104;
    float* pcr = red + 256;
    int*   flg = (int*)(pcr + 8192);

    const uint4* dqp = (const uint4*)(g_dqb + b * 1024);
    for (int j = tid; j < 128; j += 256) {
        uint4 v = __ldcg(dqp + j);
        const __nv_bfloat162* h = (const __nv_bfloat162*)&v;
#pragma unroll
        for (int k = 0; k < 4; k++) {
            float2 f = __bfloat1622float2(h[k]);
            dqs[j * 8 + k * 2]     = f.x;
            dqs[j * 8 + k * 2 + 1] = f.y;
        }
    }
    __syncthreads();

    const int hl = hlens[b];
    for (int bs = wid * 2; bs < tlen; bs += 16) {
        int t = t0 + bs;
        if (t >= hl) {
            if (lane == 0) { ws[bs] = NEGBIG; ws[bs + 1] = NEGBIG; }
            continue;
        }
        const __nv_bfloat16* r1 = g_preb + ((long long)b * 400 + t) * 1024 + lane * 8;
        const __nv_bfloat16* r2 = r1 + 1024;
        float a1 = 0.f, a2 = 0.f, a3 = 0.f, a4 = 0.f;
#pragma unroll
        for (int q = 0; q < 4; q++) {
            uint4 v1 = *(const uint4*)(r1 + q * 256);
            uint4 v2 = *(const uint4*)(r2 + q * 256);
            const __nv_bfloat162* h1 = (const __nv_bfloat162*)&v1;
            const __nv_bfloat162* h2 = (const __nv_bfloat162*)&v2;
#pragma unroll
            for (int k = 0; k < 4; k++) {
                float2 d = *(const float2*)(dqs + q * 256 + lane * 8 + k * 2);
                float2 f1 = __bfloat1622float2(h1[k]);
                float2 f2 = __bfloat1622float2(h2[k]);
                a1 = fmaf(f1.x, d.x, a1); a2 = fmaf(f1.y, d.y, a2);
                a3 = fmaf(f2.x, d.x, a3); a4 = fmaf(f2.y, d.y, a4);
            }
        }
        float s1 = a1 + a2, s2 = a3 + a4;
#pragma unroll
        for (int off = 16; off; off >>= 1) {
            s1 += __shfl_xor_sync(0xffffffffu, s1, off);
            s2 += __shfl_xor_sync(0xffffffffu, s2, off);
        }
        if (lane == 0) {
            ws[bs]     = 2.f * s1;
            ws[bs + 1] = (t + 1 < hl) ? 2.f * s2 : NEGBIG;
        }
    }
    __syncthreads();

    float lm = NEGBIG;
    for (int i = tid; i < tlen; i += 256) lm = fmaxf(lm, ws[i]);
    red[tid] = lm; __syncthreads();
    for (int st = 128; st; st >>= 1) { if (tid < st) red[tid] = fmaxf(red[tid], red[tid + st]); __syncthreads(); }
    const float m = red[0]; __syncthreads();
    float ls = 0.f;
    for (int i = tid; i < tlen; i += 256) { float w = expf(ws[i] - m); ws[i] = w; ls += w; }
    red[tid] = ls; __syncthreads();
    for (int st = 128; st; st >>= 1) { if (tid < st) red[tid] += red[tid + st]; __syncthreads(); }
    const float sl = red[0];
    __syncthreads();

    float pacc[32];
#pragma unroll
    for (int i = 0; i < 32; i++) pacc[i] = 0.f;
    for (int bs = wid * 2; bs < tlen; bs += 16) {
        if (t0 + bs >= hl) continue;
        float w1 = ws[bs], w2 = ws[bs + 1];
        const __nv_bfloat16* r1 = g_hsb + ((long long)b * 400 + t0 + bs) * 1024 + lane * 8;
        const __nv_bfloat16* r2 = r1 + 1024;
#pragma unroll
        for (int q = 0; q < 4; q++) {
            uint4 v1 = *(const uint4*)(r1 + q * 256);
            uint4 v2 = *(const uint4*)(r2 + q * 256);
            const __nv_bfloat162* h1 = (const __nv_bfloat162*)&v1;
            const __nv_bfloat162* h2 = (const __nv_bfloat162*)&v2;
#pragma unroll
            for (int k = 0; k < 4; k++) {
                float2 f1 = __bfloat1622float2(h1[k]);
                float2 f2 = __bfloat1622float2(h2[k]);
                int o = q * 8 + k * 2;
                pacc[o]     = fmaf(w1, f1.x, fmaf(w2, f2.x, pacc[o]));
                pacc[o + 1] = fmaf(w1, f1.y, fmaf(w2, f2.y, pacc[o + 1]));
            }
        }
    }
#pragma unroll
    for (int q = 0; q < 4; q++)
#pragma unroll
        for (int j = 0; j < 8; j++)
            pcr[wid * 1024 + q * 256 + lane * 8 + j] = pacc[q * 8 + j];
    __syncthreads();
    for (int col = tid; col < 1024; col += 256) {
        float a = 0.f;
#pragma unroll
        for (int w = 0; w < 8; w++) a += pcr[w * 1024 + col];
        g_pc[bid * 1024 + col] = a;
    }
    if (tid == 0) { g_ms[bid * 2] = m; g_ms[bid * 2 + 1] = sl; }
    __syncthreads();

    if (tid == 0) {
        __threadfence();
        unsigned old = atomicAdd(&g_cmb[b], 1u);
        *flg = (old == (unsigned)(s * ncs + ncs - 1)) ? 1 : 0;
    }
    __syncthreads();
    if (*flg) {
        float mi[5], si[5];
        for (int i = 0; i < ncs; i++) {
            mi[i] = __ldcg(&g_ms[(base + i) * 2]);
            si[i] = __ldcg(&g_ms[(base + i) * 2 + 1]);
        }
        float M = NEGBIG;
        for (int i = 0; i < ncs; i++) M = fmaxf(M, mi[i]);
        float sc[5], Ssum = 0.f;
        for (int i = 0; i < ncs; i++) { sc[i] = expf(mi[i] - M); Ssum += sc[i] * si[i]; }
        float inv = 1.f / Ssum;
        for (int col = tid; col < 1024; col += 256) {
            float a = 0.f;
            for (int i = 0; i < ncs; i++) a += sc[i] * __ldcg(&g_pc[(base + i) * 1024 + col]);
            __nv_bfloat16 v = __float2bfloat16(a * inv);
            g_attb[b * 1024 + col] = v;
            g_zallb[((long long)s * 32 + b) * 2048 + 1024 + col] = v;
        }
    }
    __syncthreads();
}

// ---------------------------------------------------------------- main loop (round-13)
__global__ void __launch_bounds__(256, 1) k_loop(const int* __restrict__ hlens,
                                                 const float* __restrict__ bdec) {
    extern __shared__ char sm[];
    const int bid = blockIdx.x;
    const int tid = threadIdx.x;
    int ep = 0;
    unsigned mb0 = 0;
    int par[4] = {0, 0, 0, 0};

    if (bid < 128) {
        mb0 = sptr(sm + MBAR_OFF);
        if (tid == 0) {
#pragma unroll
            for (int i = 0; i < 4; i++)
                asm volatile("mbarrier.init.shared.b64 [%0], %1;" :: "r"(mb0 + i * 8), "r"(1u) : "memory");
            asm volatile("fence.proxy.async.shared::cta;" ::: "memory");
        }
        __nv_bfloat16* pin = (__nv_bfloat16*)sm;
#pragma unroll
        for (int ci = 0; ci < 8; ci++) {
#pragma unroll
            for (int j = 0; j < 4; j++) {
                int u = tid + j * 256;
                int r = u >> 5, c = (u & 31) << 3;
                cpa16(sptr(pin + ci * 8448 + r * 264 + c),
                      g_Wc0x + (long long)(bid * 32 + r) * 2048 + ci * 256 + c);
            }
        }
        CP_COMMIT;
        CP_WAIT0;
    }
    __syncthreads();

    for (int s = 0; s <= 101; s++) {
        const int p = s & 1;
        if (bid < 128) {
            if (s >= 1)
                gtile_g1(sm + PIN, mb0, par, bid,
                         g_z0p[p], g_z1p[1 - p],
                         g_c1, g_z1p[p], g_zallb, s - 1);
        } else if (bid < 144) {
            if (s <= 100) {
                gtile_dq(sm, (bid - 128) * 64, g_Wdecb, bdec, g_z0s[p], g_dqb);
                if (tid == 0) {
                    __threadfence();
                    atomicAdd(&g_dqf, 1u);
                }
            }
        }
        if (s <= 100) {
            if (tid == 0) {
                unsigned r;
                do { asm volatile("ld.global.cg.u32 %0, [%1];" : "=r"(r) : "l"(&g_dqf)); }
                while (r < (unsigned)(16 * (s + 1)));
            }
            __syncthreads();
            phase_epc(sm + PIN, s, hlens);
        }
        gbar(ep); ep++;
        if (s == 101) break;

        if (bid < 128) {
            gtile_g0pin(sm, bid * 32, g_attb, g_z0s[p],
                        g_c0, g_z0s[1 - p], g_z0p[1 - p], s,
                        g_emb0 + (long long)s * 32 * 4096);
        }
        gbar(ep); ep++;
    }
}

// ---------------------------------------------------------------- finalize (sum of per-row LSE - tgt)
__global__ void k_fin(float* out) {
    __shared__ float red[256];
    int tid = threadIdx.x;
    float s = 0.f;
    for (int r = tid; r < L1 * BB; r += 256) {
        unsigned long long v = g_lse[r];
        float m = __int_as_float((int)(v >> 32));
        float ss = __int_as_float((int)(v & 0xffffffffULL));
        s += logf(ss) + m - g_tgtl[r];
    }
    red[tid] = s; __syncthreads();
    for (int st = 128; st; st >>= 1) { if (tid < st) red[tid] += red[tid + st]; __syncthreads(); }
    if (tid == 0) out[0] = red[0] * ((float)LL / (float)(L1 * BB));
}

// ---------------------------------------------------------------- launch
extern "C" void kernel_launch(void* const* d_in, const int* in_sizes, int n_in,
                              void* d_out, int out_size) {
    const float* hs    = (const float*)d_in[0];
    const float* embed = (const float*)d_in[1];
    const float* Wenc  = (const float*)d_in[2];
    const float* benc  = (const float*)d_in[3];
    const float* Wdec  = (const float*)d_in[4];
    const float* bdec  = (const float*)d_in[5];
    const float* Wih0  = (const float*)d_in[6];
    const float* Whh0  = (const float*)d_in[7];
    const float* bih0  = (const float*)d_in[8];
    const float* bhh0  = (const float*)d_in[9];
    const float* Wih1  = (const float*)d_in[10];
    const float* Whh1  = (const float*)d_in[11];
    const float* bih1  = (const float*)d_in[12];
    const float* bhh1  = (const float*)d_in[13];
    const float* Wout  = (const float*)d_in[14];
    const float* bout  = (const float*)d_in[15];
    const int*   hlens = (const int*)d_in[16];
    const void*  ys    = (const void*)d_in[17];

    __nv_bfloat16 *hsb, *preb, *eysb, *Wencb, *Woutb, *Wc0e, *zallb;
    float *bs0r, *emb0;
    cudaGetSymbolAddress((void**)&hsb,   g_hsb);
    cudaGetSymbolAddress((void**)&preb,  g_preb);
    cudaGetSymbolAddress((void**)&eysb,  g_eysb);
    cudaGetSymbolAddress((void**)&Wencb, g_Wencb);
    cudaGetSymbolAddress((void**)&Woutb, g_Woutb);
    cudaGetSymbolAddress((void**)&Wc0e,  g_Wc0e);
    cudaGetSymbolAddress((void**)&zallb, g_zallb);
    cudaGetSymbolAddress((void**)&bs0r,  g_bs0r);
    cudaGetSymbolAddress((void**)&emb0,  g_emb0);

    static int smem_set = 0;
    if (!smem_set) {
        cudaFuncSetAttribute(k_loop, cudaFuncAttributeMaxDynamicSharedMemorySize, SMSZ);
        cudaFuncSetAttribute(mma_big<0>, cudaFuncAttributeMaxDynamicSharedMemorySize, BIG_SMEM);
        cudaFuncSetAttribute(mma_big<1>, cudaFuncAttributeMaxDynamicSharedMemorySize, BIG_SMEM);
        cudaFuncSetAttribute(mma_big<2>, cudaFuncAttributeMaxDynamicSharedMemorySize, BIG_SMEM);
        smem_set = 1;
    }

    k_prep_all<<<296, 256>>>(hs, embed, Wenc, Wdec, Wout,
                             Wih0, Whh0, Wih1, Whh1,
                             bih0, bhh0, bih1, bhh1, ys);

    mma_big<0><<<dim3(4096 / 128, (L1 * BB + 127) / 128), 256, BIG_SMEM>>>(
        eysb, Wc0e, bs0r, emb0, nullptr, L1 * BB, 4096, 1024, nullptr);

    mma_big<1><<<dim3(DD / 128, BB * TT / 128), 256, BIG_SMEM>>>(
        hsb, Wencb, benc, nullptr, preb, BB * TT, DD, DD, nullptr);

    k_loop<<<NBLK, 256, SMSZ>>>(hlens, bdec);

    // fused out-GEMM + CE partials (no logits written)
    mma_big<2><<<dim3((VV + 127) / 128, (L1 * BB + 127) / 128), 256, BIG_SMEM>>>(
        zallb, Woutb, bout, nullptr, nullptr, L1 * BB, VV, 2048, ys);

    k_fin<<<1, 256>>>((float*)d_out);
}

// round 17
// speedup vs baseline: 1.0318x; 1.0318x over previous
#include <cuda_runtime.h>
#include <cuda_bf16.h>

#define BB 32
#define TT 400
#define DD 1024
#define VV 5000
#define LL 100
#define L1 101
#define NEGBIG -1e30f
#define NBLK 148
// smem: pinned Wc0x tile 135168B | stream region 69632B | mbarriers 32B
#define PIN 135168
#define MBAR_OFF 204800
#define SMSZ 204928
#define BIG_SMEM 110592

__device__ __align__(16) __nv_bfloat16 g_hsb [BB * TT * DD];
__device__ __align__(16) __nv_bfloat16 g_preb[BB * TT * DD];
__device__ __align__(16) __nv_bfloat16 g_eysb[L1 * BB * DD];
__device__ __align__(16) __nv_bfloat16 g_Wencb[DD * DD];
__device__ __align__(16) __nv_bfloat16 g_Wdecb[DD * DD];
__device__ __align__(16) __nv_bfloat16 g_Woutb[VV * 2048];
__device__ __align__(16) __nv_bfloat16 g_Wc0e[4096 * 1024];
__device__ __align__(16) __nv_bfloat16 g_Wc0x[4096 * 2048];
// g1 weights, padded chunk layout: [128 tiles][16 chunks][32 rows][136 cols]
__device__ __align__(16) __nv_bfloat16 g_Wc1p[128 * 16 * 32 * 136];
__device__ __align__(16) float g_bs0r[4096];
__device__ __align__(16) float g_bs1r[4096];
__device__ __align__(16) float g_emb0[(long long)L1 * BB * 4096];
__device__ __align__(16) __nv_bfloat16 g_dqb[BB * DD];
__device__ __align__(16) __nv_bfloat16 g_attb[BB * DD];
__device__ __align__(16) __nv_bfloat16 g_z0s[2][BB * DD];
// padded chunk copies for g1 A: [8 chunks][32 b][136]
__device__ __align__(16) __nv_bfloat16 g_z0p[2][8 * 32 * 136];
__device__ __align__(16) __nv_bfloat16 g_z1p[2][8 * 32 * 136];
__device__ __align__(16) float g_c0[BB * DD];
__device__ __align__(16) float g_c1[BB * DD];
__device__ __align__(16) float g_pc[148 * 1024];
__device__ __align__(16) float g_ms[304];
__device__ unsigned g_cmb[32];
__device__ __align__(16) __nv_bfloat16 g_zallb[L1 * BB * 2048];
__device__ __align__(16) float g_yall[(long long)L1 * BB * VV];
__device__ float g_loss;
__device__ int g_i64;
__device__ unsigned g_arrive;
__device__ unsigned g_release;
__device__ unsigned g_dqf;

__device__ __forceinline__ float sigm(float x) { return 1.0f / (1.0f + expf(-x)); }
__device__ __forceinline__ int read_ys(const void* ys, int i) {
    return g_i64 ? (int)((const long long*)ys)[i] : ((const int*)ys)[i];
}
__device__ __forceinline__ unsigned sptr(const void* p) {
    unsigned r;
    asm("{.reg .u64 t; cvta.to.shared.u64 t, %1; cvt.u32.u64 %0, t;}" : "=r"(r) : "l"(p));
    return r;
}
__device__ __forceinline__ void cpa16(unsigned s, const void* g) {
    asm volatile("cp.async.cg.shared.global [%0], [%1], 16;" :: "r"(s), "l"(g));
}
#define CP_COMMIT asm volatile("cp.async.commit_group;")
#define CP_WAIT2  asm volatile("cp.async.wait_group 2;")
#define CP_WAIT1  asm volatile("cp.async.wait_group 1;")
#define CP_WAIT0  asm volatile("cp.async.wait_group 0;")

#define MWAIT(mb, ph) do {                                                          \
    unsigned _done;                                                                 \
    do {                                                                            \
        asm volatile("{.reg .pred p; "                                              \
                     "mbarrier.try_wait.parity.acquire.cta.shared::cta.b64 p, [%1], %2; " \
                     "selp.b32 %0,1,0,p;}"                                          \
                     : "=r"(_done) : "r"(mb), "r"((unsigned)(ph)) : "memory");      \
    } while (!_done);                                                               \
} while (0)

__device__ __forceinline__ void bulkcp(unsigned sa, const void* g, unsigned bytes, unsigned mb) {
    asm volatile("cp.async.bulk.shared::cta.global.mbarrier::complete_tx::bytes [%0], [%1], %2, [%3];"
                 :: "r"(sa), "l"(g), "r"(bytes), "r"(mb) : "memory");
}
__device__ __forceinline__ void mexpect(unsigned mb, unsigned bytes) {
    asm volatile("mbarrier.arrive.expect_tx.shared.b64 _, [%0], %1;" :: "r"(mb), "r"(bytes) : "memory");
}

__device__ __forceinline__ unsigned pack2(float a, float b) {
    __nv_bfloat162 p = __floats2bfloat162_rn(a, b);
    return *(unsigned*)&p;
}

// ---------------------------------------------------------------- fused prologue
__global__ void k_prep_all(
    const float* __restrict__ hs, const float* __restrict__ embed,
    const float* __restrict__ Wenc, const float* __restrict__ Wdec,
    const float* __restrict__ Wout,
    const float* __restrict__ Wih0, const float* __restrict__ Whh0,
    const float* __restrict__ Wih1, const float* __restrict__ Whh1,
    const float* __restrict__ bih0, const float* __restrict__ bhh0,
    const float* __restrict__ bih1, const float* __restrict__ bhh1,
    const void* __restrict__ ys)
{
    __shared__ int s_i64;
    const int tid = threadIdx.x;
    if (tid == 0) {
        const int* w = (const int*)ys;
        int f = 1;
        for (int j = 1; j < 64; j += 2) if (w[j] != 0) f = 0;
        s_i64 = f;
    }
    __syncthreads();
    const int i64 = s_i64;
    const long long gi = (long long)blockIdx.x * blockDim.x + tid;
    const long long gn = (long long)gridDim.x * blockDim.x;

    {
        __nv_bfloat16 z = __float2bfloat16(0.f);
        for (long long j = gi; j < BB * DD; j += gn) {
            g_c0[j] = 0.f; g_c1[j] = 0.f;
            g_z0s[0][j] = z; g_z0s[1][j] = z;
        }
        for (long long j = gi; j < 8 * 32 * 136; j += gn) {
            g_z0p[0][j] = z; g_z0p[1][j] = z;
            g_z1p[0][j] = z; g_z1p[1][j] = z;
        }
        for (long long j = gi; j < 4096; j += gn) {
            int u = (int)j >> 2, gate = (int)j & 3;
            int orow = gate * 1024 + u;
            g_bs0r[j] = bih0[orow] + bhh0[orow];
            g_bs1r[j] = bih1[orow] + bhh1[orow];
        }
        if (gi < 32) g_cmb[gi] = 0u;
        if (gi == 0) { g_loss = 0.f; g_arrive = 0u; g_release = 0u; g_dqf = 0u; g_i64 = i64; }
    }
    {
        const float4* s = (const float4*)hs;
        uint4* d = (uint4*)g_hsb;
        for (long long j = gi; j < 1638400LL; j += gn) {
            float4 a = s[2 * j], b = s[2 * j + 1];
            d[j] = make_uint4(pack2(a.x, a.y), pack2(a.z, a.w), pack2(b.x, b.y), pack2(b.z, b.w));
        }
    }
    {
        const float4* s = (const float4*)Wenc;
        uint4* d = (uint4*)g_Wencb;
        for (long long j = gi; j < 131072LL; j += gn) {
            float4 a = s[2 * j], b = s[2 * j + 1];
            d[j] = make_uint4(pack2(a.x, a.y), pack2(a.z, a.w), pack2(b.x, b.y), pack2(b.z, b.w));
        }
    }
    {
        const float4* s = (const float4*)Wdec;
        uint4* d = (uint4*)g_Wdecb;
        for (long long j = gi; j < 131072LL; j += gn) {
            float4 a = s[2 * j], b = s[2 * j + 1];
            d[j] = make_uint4(pack2(a.x, a.y), pack2(a.z, a.w), pack2(b.x, b.y), pack2(b.z, b.w));
        }
    }
    {
        const float4* s = (const float4*)Wout;
        uint4* d = (uint4*)g_Woutb;
        for (long long j = gi; j < 1280000LL; j += gn) {
            float4 a = s[2 * j], b = s[2 * j + 1];
            d[j] = make_uint4(pack2(a.x, a.y), pack2(a.z, a.w), pack2(b.x, b.y), pack2(b.z, b.w));
        }
    }
    {
        for (long long it = gi; it < 413696LL; it += gn) {
            int row = (int)(it >> 7), col = (int)(it & 127);
            int l = row >> 5, b = row & 31;
            int tok = 4999;
            if (l > 0) {
                int idx = b * LL + l - 1;
                tok = i64 ? (int)((const long long*)ys)[idx] : ((const int*)ys)[idx];
            }
            float4 v = ((const float4*)(embed + (long long)tok * 1024))[col];
            ((uint2*)(g_eysb + (long long)row * 1024))[col] = make_uint2(pack2(v.x, v.y), pack2(v.z, v.w));
        }
    }
    {
        for (long long j4 = gi; j4 < 1048576LL; j4 += gn) {
            long long j = j4 * 4;
            int r = (int)(j >> 10), c = (int)(j & 1023);
            long long orow = (r & 3) * 1024 + (r >> 2);
            float4 v = *(const float4*)(Wih0 + orow * 2048 + c);
            *(uint2*)(g_Wc0e + j) = make_uint2(pack2(v.x, v.y), pack2(v.z, v.w));
        }
    }
    {
        for (long long j4 = gi; j4 < 2097152LL; j4 += gn) {
            long long j = j4 * 4;
            int r = (int)(j >> 11), c = (int)(j & 2047);
            long long orow = (r & 3) * 1024 + (r >> 2);
            float4 v = (c < 1024) ? *(const float4*)(Wih0 + orow * 2048 + 1024 + c)
                                  : *(const float4*)(Whh0 + orow * 1024 + (c - 1024));
            *(uint2*)(g_Wc0x + j) = make_uint2(pack2(v.x, v.y), pack2(v.z, v.w));
        }
    }
    // Wc1 padded chunk layout: [tile][kc][r][c], c<128 real (gate-interleaved)
    {
        const long long N4 = 128LL * 16 * 32 * 136 / 4;
        for (long long j4 = gi; j4 < N4; j4 += gn) {
            long long j = j4 * 4;
            int tile = (int)(j / 69632);
            int rem  = (int)(j % 69632);
            int kc = rem / 4352;
            int r  = (rem % 4352) / 136;
            int c  = rem % 136;
            uint2 out = make_uint2(0u, 0u);
            if (c < 128) {
                int rg = tile * 32 + r;
                long long orow = (rg & 3) * 1024 + (rg >> 2);
                int cc = kc * 128 + c;
                float4 v = (cc < 1024) ? *(const float4*)(Wih1 + orow * 1024 + cc)
                                       : *(const float4*)(Whh1 + orow * 1024 + (cc - 1024));
                out = make_uint2(pack2(v.x, v.y), pack2(v.z, v.w));
            }
            *(uint2*)(g_Wc1p + j) = out;
        }
    }
}

__device__ __forceinline__ void mma_bf16(float* d, const unsigned* a, const unsigned* b) {
    asm volatile(
        "mma.sync.aligned.m16n8k16.row.col.f32.bf16.bf16.f32 "
        "{%0,%1,%2,%3}, {%4,%5,%6,%7}, {%8,%9}, {%0,%1,%2,%3};\n"
        : "+f"(d[0]), "+f"(d[1]), "+f"(d[2]), "+f"(d[3])
        : "r"(a[0]), "r"(a[1]), "r"(a[2]), "r"(a[3]), "r"(b[0]), "r"(b[1]));
}

// ---------------------------------------------------------------- big GEMM
#define BKP 72
__device__ __forceinline__ void issue_big(
    char* smb, int slot, int k0,
    const __nv_bfloat16* A, const __nv_bfloat16* B,
    int M, int N, int K, int m0, int n0)
{
    __nv_bfloat16* smA = (__nv_bfloat16*)smb + slot * (2 * 128 * BKP);
    __nv_bfloat16* smB = smA + 128 * BKP;
    const int tid = threadIdx.x;
#pragma unroll
    for (int j = 0; j < 4; j++) {
        int idx = tid + j * 256;
        int r = idx >> 3, c = (idx & 7) * 8;
        int m = m0 + r; if (m >= M) m = 0;
        cpa16(sptr(smA + r * BKP + c), A + (long long)m * K + k0 + c);
        int n = n0 + r; if (n >= N) n = 0;
        cpa16(sptr(smB + r * BKP + c), B + (long long)n * K + k0 + c);
    }
}

template <int EPI>
__global__ __launch_bounds__(256) void mma_big(
    const __nv_bfloat16* __restrict__ A, const __nv_bfloat16* __restrict__ B,
    const float* __restrict__ bias, float* __restrict__ Cf,
    __nv_bfloat16* __restrict__ Cb, int M, int N, int K)
{
    extern __shared__ char smb[];
    const int tid = threadIdx.x, lane = tid & 31, wid = tid >> 5;
    const int wm = wid >> 1, wn = wid & 1;
    const int m0 = blockIdx.y * 128, n0 = blockIdx.x * 128;
    const int g = lane >> 2, tg = lane & 3;
    const int S = K >> 6;

    float acc[2][8][4];
#pragma unroll
    for (int a = 0; a < 2; a++)
#pragma unroll
        for (int b = 0; b < 8; b++)
#pragma unroll
            for (int c = 0; c < 4; c++) acc[a][b][c] = 0.f;

    issue_big(smb, 0, 0, A, B, M, N, K, m0, n0); CP_COMMIT;
    if (S > 1) issue_big(smb, 1, 64, A, B, M, N, K, m0, n0);
    CP_COMMIT;

    for (int si = 0; si < S; si++) {
        CP_WAIT1;
        __syncthreads();
        if (si + 2 < S) issue_big(smb, (si + 2) % 3, (si + 2) << 6, A, B, M, N, K, m0, n0);
        CP_COMMIT;
        __nv_bfloat16 (*As)[BKP] = (__nv_bfloat16(*)[BKP])((__nv_bfloat16*)smb + (si % 3) * (2 * 128 * BKP));
        __nv_bfloat16 (*Bs)[BKP] = (__nv_bfloat16(*)[BKP])((__nv_bfloat16*)smb + (si % 3) * (2 * 128 * BKP) + 128 * BKP);
#pragma unroll
        for (int kt = 0; kt < 4; kt++) {
            const int c0 = kt * 16 + tg * 2;
            unsigned af[2][4];
#pragma unroll
            for (int mt = 0; mt < 2; mt++) {
                int r = wm * 32 + mt * 16 + g;
                af[mt][0] = *(const unsigned*)&As[r][c0];
                af[mt][1] = *(const unsigned*)&As[r + 8][c0];
                af[mt][2] = *(const unsigned*)&As[r][c0 + 8];
                af[mt][3] = *(const unsigned*)&As[r + 8][c0 + 8];
            }
#pragma unroll
            for (int nt = 0; nt < 8; nt++) {
                int n = wn * 64 + nt * 8 + g;
                unsigned bf[2];
                bf[0] = *(const unsigned*)&Bs[n][c0];
                bf[1] = *(const unsigned*)&Bs[n][c0 + 8];
                mma_bf16(acc[0][nt], af[0], bf);
                mma_bf16(acc[1][nt], af[1], bf);
            }
        }
    }

#pragma unroll
    for (int mt = 0; mt < 2; mt++) {
#pragma unroll
        for (int nt = 0; nt < 8; nt++) {
            int r = m0 + wm * 32 + mt * 16 + g;
            int c = n0 + wn * 64 + nt * 8 + tg * 2;
            float* a = acc[mt][nt];
            if (EPI == 0) {
                float b0 = (c < N) ? bias[c] : 0.f;
                float b1 = (c + 1 < N) ? bias[c + 1] : 0.f;
                if (r < M) {
                    if (c < N)     Cf[(long long)r * N + c]     = a[0] + b0;
                    if (c + 1 < N) Cf[(long long)r * N + c + 1] = a[1] + b1;
                }
                if (r + 8 < M) {
                    if (c < N)     Cf[(long long)(r + 8) * N + c]     = a[2] + b0;
                    if (c + 1 < N) Cf[(long long)(r + 8) * N + c + 1] = a[3] + b1;
                }
            } else {
                float b0 = bias[c], b1 = bias[c + 1];
                __nv_bfloat162 v0 = __floats2bfloat162_rn(tanhf(a[0] + b0), tanhf(a[1] + b1));
                __nv_bfloat162 v1 = __floats2bfloat162_rn(tanhf(a[2] + b0), tanhf(a[3] + b1));
                *(__nv_bfloat162*)(Cb + (long long)r * N + c) = v0;
                *(__nv_bfloat162*)(Cb + (long long)(r + 8) * N + c) = v1;
            }
        }
    }
}

// ---------------------------------------------------------------- fused prologue GEMMs
// blocks [0, 832): emb0 = eysb @ Wc0e^T + bs0r (fp32 out, M=3232, N=4096)
// blocks [832, 1632): preb = tanh(hsb @ Wencb^T + benc) (bf16 out, M=12800, N=1024)
__global__ __launch_bounds__(256) void mma_dual(const float* __restrict__ benc)
{
    extern __shared__ char smb[];
    const int bid = blockIdx.x;
    const int tid = threadIdx.x, lane = tid & 31, wid = tid >> 5;
    const int wm = wid >> 1, wn = wid & 1;
    const int g = lane >> 2, tg = lane & 3;
    const int K = 1024, S = 16;

    const __nv_bfloat16 *A, *B;
    const float* bias;
    int M, N, m0, n0, epi;
    if (bid < 832) {
        epi = 0;
        m0 = (bid >> 5) * 128; n0 = (bid & 31) * 128;
        A = g_eysb; B = g_Wc0e; bias = g_bs0r;
        M = L1 * BB; N = 4096;
    } else {
        epi = 1;
        int b2 = bid - 832;
        m0 = (b2 >> 3) * 128; n0 = (b2 & 7) * 128;
        A = g_hsb; B = g_Wencb; bias = benc;
        M = BB * TT; N = 1024;
    }

    float acc[2][8][4];
#pragma unroll
    for (int a = 0; a < 2; a++)
#pragma unroll
        for (int b = 0; b < 8; b++)
#pragma unroll
            for (int c = 0; c < 4; c++) acc[a][b][c] = 0.f;

    issue_big(smb, 0, 0, A, B, M, N, K, m0, n0); CP_COMMIT;
    issue_big(smb, 1, 64, A, B, M, N, K, m0, n0); CP_COMMIT;

    for (int si = 0; si < S; si++) {
        CP_WAIT1;
        __syncthreads();
        if (si + 2 < S) issue_big(smb, (si + 2) % 3, (si + 2) << 6, A, B, M, N, K, m0, n0);
        CP_COMMIT;
        __nv_bfloat16 (*As)[BKP] = (__nv_bfloat16(*)[BKP])((__nv_bfloat16*)smb + (si % 3) * (2 * 128 * BKP));
        __nv_bfloat16 (*Bs)[BKP] = (__nv_bfloat16(*)[BKP])((__nv_bfloat16*)smb + (si % 3) * (2 * 128 * BKP) + 128 * BKP);
#pragma unroll
        for (int kt = 0; kt < 4; kt++) {
            const int c0 = kt * 16 + tg * 2;
            unsigned af[2][4];
#pragma unroll
            for (int mt = 0; mt < 2; mt++) {
                int r = wm * 32 + mt * 16 + g;
                af[mt][0] = *(const unsigned*)&As[r][c0];
                af[mt][1] = *(const unsigned*)&As[r + 8][c0];
                af[mt][2] = *(const unsigned*)&As[r][c0 + 8];
                af[mt][3] = *(const unsigned*)&As[r + 8][c0 + 8];
            }
#pragma unroll
            for (int nt = 0; nt < 8; nt++) {
                int n = wn * 64 + nt * 8 + g;
                unsigned bf[2];
                bf[0] = *(const unsigned*)&Bs[n][c0];
                bf[1] = *(const unsigned*)&Bs[n][c0 + 8];
                mma_bf16(acc[0][nt], af[0], bf);
                mma_bf16(acc[1][nt], af[1], bf);
            }
        }
    }

#pragma unroll
    for (int mt = 0; mt < 2; mt++) {
#pragma unroll
        for (int nt = 0; nt < 8; nt++) {
            int r = m0 + wm * 32 + mt * 16 + g;
            int c = n0 + wn * 64 + nt * 8 + tg * 2;
            float* a = acc[mt][nt];
            if (epi == 0) {
                float b0 = bias[c], b1 = bias[c + 1];
                if (r < M) {
                    g_emb0[(long long)r * 4096 + c]     = a[0] + b0;
                    g_emb0[(long long)r * 4096 + c + 1] = a[1] + b1;
                }
                if (r + 8 < M) {
                    g_emb0[(long long)(r + 8) * 4096 + c]     = a[2] + b0;
                    g_emb0[(long long)(r + 8) * 4096 + c + 1] = a[3] + b1;
                }
            } else {
                float b0 = bias[c], b1 = bias[c + 1];
                __nv_bfloat162 v0 = __floats2bfloat162_rn(tanhf(a[0] + b0), tanhf(a[1] + b1));
                __nv_bfloat162 v1 = __floats2bfloat162_rn(tanhf(a[2] + b0), tanhf(a[3] + b1));
                *(__nv_bfloat162*)(g_preb + (long long)r * 1024 + c) = v0;
                *(__nv_bfloat162*)(g_preb + (long long)(r + 8) * 1024 + c) = v1;
            }
        }
    }
}

// ---------------------------------------------------------------- barrier
__device__ __forceinline__ void gbar(int e) {
    __syncthreads();
    if (threadIdx.x == 0) {
        __threadfence();
        unsigned old = atomicAdd(&g_arrive, 1u);
        if (old == (unsigned)e * NBLK + (NBLK - 1)) {
            atomicExch(&g_release, (unsigned)(e + 1));
        } else {
            unsigned r;
            do { asm volatile("ld.global.cg.u32 %0, [%1];" : "=r"(r) : "l"(&g_release)); }
            while (r < (unsigned)(e + 1));
        }
        __threadfence();
    }
    __syncthreads();
}

// ---------------------------------------------------------------- dq tile GEMM (cp.async)
__device__ __forceinline__ void issue_dq(char* smraw, int slot, int kc,
                                         const __nv_bfloat16* A0, const __nv_bfloat16* B, int n0)
{
    constexpr int ASZ = 32 * 264;
    constexpr int STE = ASZ + 64 * 264;
    __nv_bfloat16* smA = (__nv_bfloat16*)smraw + slot * STE;
    __nv_bfloat16* smB = smA + ASZ;
    const int tid = threadIdx.x;
    const int kbase = kc << 8;
#pragma unroll
    for (int j = 0; j < 4; j++) {
        int u = tid + j * 256;
        int r = u >> 5, c = (u & 31) << 3;
        cpa16(sptr(smA + r * 264 + c), A0 + r * 1024 + kbase + c);
    }
#pragma unroll
    for (int j = 0; j < 8; j++) {
        int u = tid + j * 256;
        int r = u >> 5, c = (u & 31) << 3;
        cpa16(sptr(smB + r * 264 + c), B + (long long)(n0 + r) * 1024 + kbase + c);
    }
}

__device__ void gtile_dq(char* smraw, int n0, const __nv_bfloat16* __restrict__ B,
                         const float* __restrict__ bias, const __nv_bfloat16* A0,
                         __nv_bfloat16* outb)
{
    constexpr int ASZ = 32 * 264;
    constexpr int STE = ASZ + 64 * 264;
    constexpr int NW = 32 * 64;
    const int tid = threadIdx.x, lane = tid & 31, wid = tid >> 5;
    const int g = lane >> 2, tg = lane & 3;
    const int S = 4;

    float acc[2][8][4];
#pragma unroll
    for (int a = 0; a < 2; a++)
#pragma unroll
        for (int b = 0; b < 8; b++)
#pragma unroll
            for (int c = 0; c < 4; c++) acc[a][b][c] = 0.f;

#pragma unroll
    for (int st = 0; st < 3; st++) {
        if (st < S) issue_dq(smraw, st, st, A0, B, n0);
        CP_COMMIT;
    }

    for (int si = 0; si < S; si++) {
        CP_WAIT2;
        __syncthreads();
        int nx = si + 3;
        if (nx < S) issue_dq(smraw, nx & 3, nx, A0, B, n0);
        CP_COMMIT;
        __nv_bfloat16 (*As)[264] = (__nv_bfloat16(*)[264])((__nv_bfloat16*)smraw + (si & 3) * STE);
        __nv_bfloat16 (*Bs)[264] = (__nv_bfloat16(*)[264])((__nv_bfloat16*)smraw + (si & 3) * STE + ASZ);
#pragma unroll
        for (int ks = 0; ks < 2; ks++) {
            const int c0 = wid * 32 + ks * 16 + tg * 2;
            unsigned af[2][4];
#pragma unroll
            for (int mt = 0; mt < 2; mt++) {
                int r = mt * 16 + g;
                af[mt][0] = *(const unsigned*)&As[r][c0];
                af[mt][1] = *(const unsigned*)&As[r + 8][c0];
                af[mt][2] = *(const unsigned*)&As[r][c0 + 8];
                af[mt][3] = *(const unsigned*)&As[r + 8][c0 + 8];
            }
#pragma unroll
            for (int nt = 0; nt < 8; nt++) {
                int n = nt * 8 + g;
                unsigned bf[2];
                bf[0] = *(const unsigned*)&Bs[n][c0];
                bf[1] = *(const unsigned*)&Bs[n][c0 + 8];
                mma_bf16(acc[0][nt], af[0], bf);
                mma_bf16(acc[1][nt], af[1], bf);
            }
        }
    }
    __syncthreads();

    float* Pred = (float*)smraw;
    {
        int base = wid * NW;
#pragma unroll
        for (int mt = 0; mt < 2; mt++)
#pragma unroll
            for (int nt = 0; nt < 8; nt++) {
                int r = mt * 16 + g, cl = nt * 8 + tg * 2;
                Pred[base + r * 64 + cl]           = acc[mt][nt][0];
                Pred[base + r * 64 + cl + 1]       = acc[mt][nt][1];
                Pred[base + (r + 8) * 64 + cl]     = acc[mt][nt][2];
                Pred[base + (r + 8) * 64 + cl + 1] = acc[mt][nt][3];
            }
    }
    __syncthreads();

    for (int o = tid; o < NW; o += 256) {
        int r = o >> 6, c = o & 63;
        float sum = 0.f;
#pragma unroll
        for (int w = 0; w < 8; w++) sum += Pred[w * NW + o];
        outb[r * 1024 + n0 + c] = __float2bfloat16(tanhf(sum + bias[n0 + c]));
    }
    __syncthreads();
}

// ---------------------------------------------------------------- g1: bulk-copy + mbarrier pipeline
__device__ __forceinline__ void issue_g1b(char* stream, unsigned mbar0, int kc,
                                          const __nv_bfloat16* z0p, const __nv_bfloat16* z1p,
                                          const __nv_bfloat16* Bw)
{
    unsigned mb = mbar0 + (kc & 3) * 8;
    mexpect(mb, 17408u);
    const __nv_bfloat16* asrc = (kc < 8) ? (z0p + kc * 4352) : (z1p + (kc - 8) * 4352);
    unsigned sa = sptr(stream + (kc & 3) * 17408);
    bulkcp(sa, asrc, 8704u, mb);
    bulkcp(sa + 8704u, Bw + kc * 4352, 8704u, mb);
}

__device__ void gtile_g1(char* stream, unsigned mbar0, int* par, int tile,
                         const __nv_bfloat16* z0p, const __nv_bfloat16* z1p,
                         float* cst, __nv_bfloat16* z1po, __nv_bfloat16* zallp, int step)
{
    const int tid = threadIdx.x, lane = tid & 31, wid = tid >> 5;
    const int g = lane >> 2, tg = lane & 3;
    const __nv_bfloat16* Bw = g_Wc1p + (long long)tile * 69632;

    float acc[2][4][4];
#pragma unroll
    for (int a = 0; a < 2; a++)
#pragma unroll
        for (int b = 0; b < 4; b++)
#pragma unroll
            for (int c = 0; c < 4; c++) acc[a][b][c] = 0.f;

    if (tid == 0) {
        issue_g1b(stream, mbar0, 0, z0p, z1p, Bw);
        issue_g1b(stream, mbar0, 1, z0p, z1p, Bw);
        issue_g1b(stream, mbar0, 2, z0p, z1p, Bw);
    }

    for (int si = 0; si < 16; si++) {
        {
            unsigned mb = mbar0 + (si & 3) * 8;
            MWAIT(mb, par[si & 3]);
            par[si & 3] ^= 1;
        }
        __syncthreads();
        if (tid == 0 && si + 3 < 16) issue_g1b(stream, mbar0, si + 3, z0p, z1p, Bw);
        __nv_bfloat16 (*As)[136] = (__nv_bfloat16(*)[136])(stream + (si & 3) * 17408);
        __nv_bfloat16 (*Bs)[136] = (__nv_bfloat16(*)[136])(stream + (si & 3) * 17408 + 8704);
        const int c0 = wid * 16 + tg * 2;
        unsigned af[2][4];
#pragma unroll
        for (int mt = 0; mt < 2; mt++) {
            int r = mt * 16 + g;
            af[mt][0] = *(const unsigned*)&As[r][c0];
            af[mt][1] = *(const unsigned*)&As[r + 8][c0];
            af[mt][2] = *(const unsigned*)&As[r][c0 + 8];
            af[mt][3] = *(const unsigned*)&As[r + 8][c0 + 8];
        }
#pragma unroll
        for (int nt = 0; nt < 4; nt++) {
            int n = nt * 8 + g;
            unsigned bf[2];
            bf[0] = *(const unsigned*)&Bs[n][c0];
            bf[1] = *(const unsigned*)&Bs[n][c0 + 8];
            mma_bf16(acc[0][nt], af[0], bf);
            mma_bf16(acc[1][nt], af[1], bf);
        }
    }
    __syncthreads();

    float* Pred = (float*)stream;
    {
        int base = wid * 1024;
#pragma unroll
        for (int mt = 0; mt < 2; mt++)
#pragma unroll
            for (int nt = 0; nt < 4; nt++) {
                int r = mt * 16 + g, cl = nt * 8 + tg * 2;
                Pred[base + r * 32 + cl]           = acc[mt][nt][0];
                Pred[base + r * 32 + cl + 1]       = acc[mt][nt][1];
                Pred[base + (r + 8) * 32 + cl]     = acc[mt][nt][2];
                Pred[base + (r + 8) * 32 + cl + 1] = acc[mt][nt][3];
            }
    }
    __syncthreads();
    {
        const int n0 = tile * 32;
        int b = tid >> 3, ul = tid & 7;
        float gv[4];
#pragma unroll
        for (int gate = 0; gate < 4; gate++) {
            int col = ul * 4 + gate;
            float sum = 0.f;
#pragma unroll
            for (int w = 0; w < 8; w++) sum += Pred[w * 1024 + b * 32 + col];
            gv[gate] = sum + g_bs1r[n0 + col];
        }
        int u = (n0 >> 2) + ul;
        int gid = b * 1024 + u;
        float cv = sigm(gv[1]) * cst[gid] + sigm(gv[0]) * tanhf(gv[2]);
        float h = sigm(gv[3]) * tanhf(cv);
        cst[gid] = cv;
        z1po[(u >> 7) * 4352 + b * 136 + (u & 127)] = __float2bfloat16(h);
        zallp[(long long)(step * 32 + b) * 2048 + u] = __float2bfloat16(h);
    }
    __syncthreads();
}

// ---------------------------------------------------------------- g0 (B pinned, A cp.async)
__device__ __forceinline__ void issue_g0a(char* strm, int slot, int kc,
                                          const __nv_bfloat16* A0, const __nv_bfloat16* A1)
{
    __nv_bfloat16* smA = (__nv_bfloat16*)strm + slot * (32 * 264);
    const int tid = threadIdx.x;
    const int kbase = kc << 8;
    const int region = kbase >> 10;
    const int koff = kbase & 1023;
#pragma unroll
    for (int j = 0; j < 4; j++) {
        int u = tid + j * 256;
        int r = u >> 5, c = (u & 31) << 3;
        const __nv_bfloat16* src = (region == 0 ? A0 : A1) + r * 1024 + koff + c;
        cpa16(sptr(smA + r * 264 + c), src);
    }
}

__device__ void gtile_g0pin(char* sm, int n0,
                            const __nv_bfloat16* A0, const __nv_bfloat16* A1,
                            float* cst, __nv_bfloat16* znew, __nv_bfloat16* z0po,
                            int step, const float* eb)
{
    char* strm = sm + PIN;
    const int tid = threadIdx.x, lane = tid & 31, wid = tid >> 5;
    const int g = lane >> 2, tg = lane & 3;
    const int S = 8;

    float acc[2][4][4];
#pragma unroll
    for (int a = 0; a < 2; a++)
#pragma unroll
        for (int b = 0; b < 4; b++)
#pragma unroll
            for (int c = 0; c < 4; c++) acc[a][b][c] = 0.f;

#pragma unroll
    for (int st = 0; st < 3; st++) {
        issue_g0a(strm, st, st, A0, A1);
        CP_COMMIT;
    }

    for (int si = 0; si < S; si++) {
        CP_WAIT2;
        __syncthreads();
        int nx = si + 3;
        if (nx < S) issue_g0a(strm, nx & 3, nx, A0, A1);
        CP_COMMIT;
        __nv_bfloat16 (*As)[264] = (__nv_bfloat16(*)[264])((__nv_bfloat16*)strm + (si & 3) * (32 * 264));
        __nv_bfloat16 (*Bs)[264] = (__nv_bfloat16(*)[264])((__nv_bfloat16*)sm + si * (32 * 264));
#pragma unroll
        for (int ks = 0; ks < 2; ks++) {
            const int c0 = wid * 32 + ks * 16 + tg * 2;
            unsigned af[2][4];
#pragma unroll
            for (int mt = 0; mt < 2; mt++) {
                int r = mt * 16 + g;
                af[mt][0] = *(const unsigned*)&As[r][c0];
                af[mt][1] = *(const unsigned*)&As[r + 8][c0];
                af[mt][2] = *(const unsigned*)&As[r][c0 + 8];
                af[mt][3] = *(const unsigned*)&As[r + 8][c0 + 8];
            }
#pragma unroll
            for (int nt = 0; nt < 4; nt++) {
                int n = nt * 8 + g;
                unsigned bf[2];
                bf[0] = *(const unsigned*)&Bs[n][c0];
                bf[1] = *(const unsigned*)&Bs[n][c0 + 8];
                mma_bf16(acc[0][nt], af[0], bf);
                mma_bf16(acc[1][nt], af[1], bf);
            }
        }
    }
    __syncthreads();

    float* Pred = (float*)strm;
    {
        int base = wid * 1024;
#pragma unroll
        for (int mt = 0; mt < 2; mt++)
#pragma unroll
            for (int nt = 0; nt < 4; nt++) {
                int r = mt * 16 + g, cl = nt * 8 + tg * 2;
                Pred[base + r * 32 + cl]           = acc[mt][nt][0];
                Pred[base + r * 32 + cl + 1]       = acc[mt][nt][1];
                Pred[base + (r + 8) * 32 + cl]     = acc[mt][nt][2];
                Pred[base + (r + 8) * 32 + cl + 1] = acc[mt][nt][3];
            }
    }
    __syncthreads();
    {
        int b = tid >> 3, ul = tid & 7;
        float gv[4];
#pragma unroll
        for (int gate = 0; gate < 4; gate++) {
            int col = ul * 4 + gate;
            float sum = 0.f;
#pragma unroll
            for (int w = 0; w < 8; w++) sum += Pred[w * 1024 + b * 32 + col];
            gv[gate] = sum + eb[b * 4096 + n0 + col];
        }
        int u = (n0 >> 2) + ul;
        int gid = b * 1024 + u;
        float cv = sigm(gv[1]) * cst[gid] + sigm(gv[0]) * tanhf(gv[2]);
        float h = sigm(gv[3]) * tanhf(cv);
        cst[gid] = cv;
        __nv_bfloat16 hb = __float2bfloat16(h);
        znew[gid] = hb;
        z0po[(u >> 7) * 4352 + b * 136 + (u & 127)] = hb;
    }
    __syncthreads();
}

// ---------------------------------------------------------------- attention (hlen-skip)
__device__ void phase_epc(char* smraw, int s, const int* __restrict__ hlens) {
    const int bid = blockIdx.x;
    int b, t0, tlen, ncs, base;
    if (bid < 100) { b = bid / 5; t0 = (bid % 5) * 80; tlen = 80; ncs = 5; base = b * 5; }
    else { int u = bid - 100; b = 20 + (u >> 2); t0 = (u & 3) * 100; tlen = 100; ncs = 4; base = 100 + (b - 20) * 4; }

    const int tid = threadIdx.x, lane = tid & 31, wid = tid >> 5;
    float* dqs = (float*)smraw;
    float* ws  = dqs + 1024;
    float* red = ws + 104;
    float* pcr = red + 256;
    int*   flg = (int*)(pcr + 8192);

    const uint4* dqp = (const uint4*)(g_dqb + b * 1024);
    for (int j = tid; j < 128; j += 256) {
        uint4 v = __ldcg(dqp + j);
        const __nv_bfloat162* h = (const __nv_bfloat162*)&v;
#pragma unroll
        for (int k = 0; k < 4; k++) {
            float2 f = __bfloat1622float2(h[k]);
            dqs[j * 8 + k * 2]     = f.x;
            dqs[j * 8 + k * 2 + 1] = f.y;
        }
    }
    __syncthreads();

    const int hl = hlens[b];
    for (int bs = wid * 2; bs < tlen; bs += 16) {
        int t = t0 + bs;
        if (t >= hl) {
            if (lane == 0) { ws[bs] = NEGBIG; ws[bs + 1] = NEGBIG; }
            continue;
        }
        const __nv_bfloat16* r1 = g_preb + ((long long)b * 400 + t) * 1024 + lane * 8;
        const __nv_bfloat16* r2 = r1 + 1024;
        float a1 = 0.f, a2 = 0.f, a3 = 0.f, a4 = 0.f;
#pragma unroll
        for (int q = 0; q < 4; q++) {
            uint4 v1 = *(const uint4*)(r1 + q * 256);
            uint4 v2 = *(const uint4*)(r2 + q * 256);
            const __nv_bfloat162* h1 = (const __nv_bfloat162*)&v1;
            const __nv_bfloat162* h2 = (const __nv_bfloat162*)&v2;
#pragma unroll
            for (int k = 0; k < 4; k++) {
                float2 d = *(const float2*)(dqs + q * 256 + lane * 8 + k * 2);
                float2 f1 = __bfloat1622float2(h1[k]);
                float2 f2 = __bfloat1622float2(h2[k]);
                a1 = fmaf(f1.x, d.x, a1); a2 = fmaf(f1.y, d.y, a2);
                a3 = fmaf(f2.x, d.x, a3); a4 = fmaf(f2.y, d.y, a4);
            }
        }
        float s1 = a1 + a2, s2 = a3 + a4;
#pragma unroll
        for (int off = 16; off; off >>= 1) {
            s1 += __shfl_xor_sync(0xffffffffu, s1, off);
            s2 += __shfl_xor_sync(0xffffffffu, s2, off);
        }
        if (lane == 0) {
            ws[bs]     = 2.f * s1;
            ws[bs + 1] = (t + 1 < hl) ? 2.f * s2 : NEGBIG;
        }
    }
    __syncthreads();

    float lm = NEGBIG;
    for (int i = tid; i < tlen; i += 256) lm = fmaxf(lm, ws[i]);
    red[tid] = lm; __syncthreads();
    for (int st = 128; st; st >>= 1) { if (tid < st) red[tid] = fmaxf(red[tid], red[tid + st]); __syncthreads(); }
    const float m = red[0]; __syncthreads();
    float ls = 0.f;
    for (int i = tid; i < tlen; i += 256) { float w = expf(ws[i] - m); ws[i] = w; ls += w; }
    red[tid] = ls; __syncthreads();
    for (int st = 128; st; st >>= 1) { if (tid < st) red[tid] += red[tid + st]; __syncthreads(); }
    const float sl = red[0];
    __syncthreads();

    float pacc[32];
#pragma unroll
    for (int i = 0; i < 32; i++) pacc[i] = 0.f;
    for (int bs = wid * 2; bs < tlen; bs += 16) {
        if (t0 + bs >= hl) continue;
        float w1 = ws[bs], w2 = ws[bs + 1];
        const __nv_bfloat16* r1 = g_hsb + ((long long)b * 400 + t0 + bs) * 1024 + lane * 8;
        const __nv_bfloat16* r2 = r1 + 1024;
#pragma unroll
        for (int q = 0; q < 4; q++) {
            uint4 v1 = *(const uint4*)(r1 + q * 256);
            uint4 v2 = *(const uint4*)(r2 + q * 256);
            const __nv_bfloat162* h1 = (const __nv_bfloat162*)&v1;
            const __nv_bfloat162* h2 = (const __nv_bfloat162*)&v2;
#pragma unroll
            for (int k = 0; k < 4; k++) {
                float2 f1 = __bfloat1622float2(h1[k]);
                float2 f2 = __bfloat1622float2(h2[k]);
                int o = q * 8 + k * 2;
                pacc[o]     = fmaf(w1, f1.x, fmaf(w2, f2.x, pacc[o]));
                pacc[o + 1] = fmaf(w1, f1.y, fmaf(w2, f2.y, pacc[o + 1]));
            }
        }
    }
#pragma unroll
    for (int q = 0; q < 4; q++)
#pragma unroll
        for (int j = 0; j < 8; j++)
            pcr[wid * 1024 + q * 256 + lane * 8 + j] = pacc[q * 8 + j];
    __syncthreads();
    for (int col = tid; col < 1024; col += 256) {
        float a = 0.f;
#pragma unroll
        for (int w = 0; w < 8; w++) a += pcr[w * 1024 + col];
        g_pc[bid * 1024 + col] = a;
    }
    if (tid == 0) { g_ms[bid * 2] = m; g_ms[bid * 2 + 1] = sl; }
    __syncthreads();

    if (tid == 0) {
        __threadfence();
        unsigned old = atomicAdd(&g_cmb[b], 1u);
        *flg = (old == (unsigned)(s * ncs + ncs - 1)) ? 1 : 0;
    }
    __syncthreads();
    if (*flg) {
        float mi[5], si[5];
        for (int i = 0; i < ncs; i++) {
            mi[i] = __ldcg(&g_ms[(base + i) * 2]);
            si[i] = __ldcg(&g_ms[(base + i) * 2 + 1]);
        }
        float M = NEGBIG;
        for (int i = 0; i < ncs; i++) M = fmaxf(M, mi[i]);
        float sc[5], Ssum = 0.f;
        for (int i = 0; i < ncs; i++) { sc[i] = expf(mi[i] - M); Ssum += sc[i] * si[i]; }
        float inv = 1.f / Ssum;
        for (int col = tid; col < 1024; col += 256) {
            float a = 0.f;
            for (int i = 0; i < ncs; i++) a += sc[i] * __ldcg(&g_pc[(base + i) * 1024 + col]);
            __nv_bfloat16 v = __float2bfloat16(a * inv);
            g_attb[b * 1024 + col] = v;
            g_zallb[((long long)s * 32 + b) * 2048 + 1024 + col] = v;
        }
    }
    __syncthreads();
}

// ---------------------------------------------------------------- main loop
__global__ void __launch_bounds__(256, 1) k_loop(const int* __restrict__ hlens,
                                                 const float* __restrict__ bdec) {
    extern __shared__ char sm[];
    const int bid = blockIdx.x;
    const int tid = threadIdx.x;
    int ep = 0;
    unsigned mb0 = 0;
    int par[4] = {0, 0, 0, 0};

    if (bid < 128) {
        mb0 = sptr(sm + MBAR_OFF);
        if (tid == 0) {
#pragma unroll
            for (int i = 0; i < 4; i++)
                asm volatile("mbarrier.init.shared.b64 [%0], %1;" :: "r"(mb0 + i * 8), "r"(1u) : "memory");
            asm volatile("fence.proxy.async.shared::cta;" ::: "memory");
        }
        __nv_bfloat16* pin = (__nv_bfloat16*)sm;
#pragma unroll
        for (int ci = 0; ci < 8; ci++) {
#pragma unroll
            for (int j = 0; j < 4; j++) {
                int u = tid + j * 256;
                int r = u >> 5, c = (u & 31) << 3;
                cpa16(sptr(pin + ci * 8448 + r * 264 + c),
                      g_Wc0x + (long long)(bid * 32 + r) * 2048 + ci * 256 + c);
            }
        }
        CP_COMMIT;
        CP_WAIT0;
    }
    __syncthreads();

    for (int s = 0; s <= 101; s++) {
        const int p = s & 1;
        if (bid < 128) {
            if (s >= 1)
                gtile_g1(sm + PIN, mb0, par, bid,
                         g_z0p[p], g_z1p[1 - p],
                         g_c1, g_z1p[p], g_zallb, s - 1);
        } else if (bid < 144) {
            if (s <= 100) {
                gtile_dq(sm, (bid - 128) * 64, g_Wdecb, bdec, g_z0s[p], g_dqb);
                if (tid == 0) {
                    __threadfence();
                    atomicAdd(&g_dqf, 1u);
                }
            }
        }
        if (s <= 100) {
            if (tid == 0) {
                unsigned r;
                do { asm volatile("ld.global.cg.u32 %0, [%1];" : "=r"(r) : "l"(&g_dqf)); }
                while (r < (unsigned)(16 * (s + 1)));
            }
            __syncthreads();
            phase_epc(sm + PIN, s, hlens);
        }
        gbar(ep); ep++;
        if (s == 101) break;

        if (bid < 128) {
            gtile_g0pin(sm, bid * 32, g_attb, g_z0s[p],
                        g_c0, g_z0s[1 - p], g_z0p[1 - p], s,
                        g_emb0 + (long long)s * 32 * 4096);
        }
        gbar(ep); ep++;
    }
}

// ---------------------------------------------------------------- CE
__global__ void k_ce(const void* __restrict__ ys) {
    int r = blockIdx.x;
    int l = r / BB, b = r % BB;
    const float* y = g_yall + (long long)r * VV;
    __shared__ float red[256];
    int tid = threadIdx.x;
    float lm = NEGBIG;
    for (int v = tid; v < VV; v += 256) lm = fmaxf(lm, y[v]);
    red[tid] = lm; __syncthreads();
    for (int s = 128; s > 0; s >>= 1) { if (tid < s) red[tid] = fmaxf(red[tid], red[tid + s]); __syncthreads(); }
    float m = red[0]; __syncthreads();
    float ls = 0.f;
    for (int v = tid; v < VV; v += 256) ls += expf(y[v] - m);
    red[tid] = ls; __syncthreads();
    for (int s = 128; s > 0; s >>= 1) { if (tid < s) red[tid] += red[tid + s]; __syncthreads(); }
    if (tid == 0) {
        int tgt = (l < LL) ? read_ys(ys, b * LL + l) : 4999;
        atomicAdd(&g_loss, logf(red[0]) + m - y[tgt]);
    }
}

__global__ void k_fin(float* out) {
    out[0] = g_loss * ((float)LL / (float)(L1 * BB));
}

// ---------------------------------------------------------------- launch
extern "C" void kernel_launch(void* const* d_in, const int* in_sizes, int n_in,
                              void* d_out, int out_size) {
    const float* hs    = (const float*)d_in[0];
    const float* embed = (const float*)d_in[1];
    const float* Wenc  = (const float*)d_in[2];
    const float* benc  = (const float*)d_in[3];
    const float* Wdec  = (const float*)d_in[4];
    const float* bdec  = (const float*)d_in[5];
    const float* Wih0  = (const float*)d_in[6];
    const float* Whh0  = (const float*)d_in[7];
    const float* bih0  = (const float*)d_in[8];
    const float* bhh0  = (const float*)d_in[9];
    const float* Wih1  = (const float*)d_in[10];
    const float* Whh1  = (const float*)d_in[11];
    const float* bih1  = (const float*)d_in[12];
    const float* bhh1  = (const float*)d_in[13];
    const float* Wout  = (const float*)d_in[14];
    const float* bout  = (const float*)d_in[15];
    const int*   hlens = (const int*)d_in[16];
    const void*  ys    = (const void*)d_in[17];

    __nv_bfloat16 *Woutb, *zallb;
    float *yall;
    cudaGetSymbolAddress((void**)&Woutb, g_Woutb);
    cudaGetSymbolAddress((void**)&zallb, g_zallb);
    cudaGetSymbolAddress((void**)&yall,  g_yall);

    static int smem_set = 0;
    if (!smem_set) {
        cudaFuncSetAttribute(k_loop, cudaFuncAttributeMaxDynamicSharedMemorySize, SMSZ);
        cudaFuncSetAttribute(mma_big<0>, cudaFuncAttributeMaxDynamicSharedMemorySize, BIG_SMEM);
        cudaFuncSetAttribute(mma_big<1>, cudaFuncAttributeMaxDynamicSharedMemorySize, BIG_SMEM);
        cudaFuncSetAttribute(mma_dual, cudaFuncAttributeMaxDynamicSharedMemorySize, BIG_SMEM);
        smem_set = 1;
    }

    k_prep_all<<<296, 256>>>(hs, embed, Wenc, Wdec, Wout,
                             Wih0, Whh0, Wih1, Whh1,
                             bih0, bhh0, bih1, bhh1, ys);

    // fused prologue GEMMs: emb0 (832 blocks) + pre_enc (800 blocks)
    mma_dual<<<1632, 256, BIG_SMEM>>>(benc);

    k_loop<<<NBLK, 256, SMSZ>>>(hlens, bdec);

    mma_big<0><<<dim3((VV + 127) / 128, (L1 * BB + 127) / 128), 256, BIG_SMEM>>>(
        zallb, Woutb, bout, yall, nullptr, L1 * BB, VV, 2048);

    k_ce<<<L1 * BB, 256>>>(ys);
    k_fin<<<1, 1>>>((float*)d_out);
}